// round 4
// baseline (speedup 1.0000x reference)
#include <cuda_runtime.h>
#include <cuda_bf16.h>

#define NHEAD 16
#define DIM   64
#define BS    64
#define NSEL  16
#define SCALE 0.125f
#define PAD   68   // floats per padded smem row (17 x 16B units, odd -> conflict-free)

__global__ __launch_bounds__(128, 4)
void nsa_kernel(const float* __restrict__ Q, const float* __restrict__ K,
                const float* __restrict__ V, const int* __restrict__ BIdx,
                float* __restrict__ Out)
{
    const int t   = blockIdx.x;
    const int tid = threadIdx.x;

    __shared__ __align__(16) float Qs[NHEAD][PAD];
    __shared__ __align__(16) float Ks[BS][PAD];
    __shared__ __align__(16) float Vs[BS][PAD];
    __shared__ __align__(16) float Ss[NHEAD][PAD];
    __shared__ float mS[NHEAD], lS[NHEAD], aS[NHEAD];
    __shared__ int   blkS[NSEL];

    // ---- load Q tile (16x64 floats = 256 float4, 2 per thread) ----
    {
        const float4* Qg = reinterpret_cast<const float4*>(Q + (size_t)t * NHEAD * DIM);
        #pragma unroll
        for (int i = 0; i < 2; ++i) {
            int e = tid + i * 128;
            int h = e >> 4, c4 = e & 15;
            float4 v = Qg[e];
            *reinterpret_cast<float4*>(&Qs[h][c4 * 4]) = v;
        }
    }
    if (tid < NSEL)  blkS[tid] = BIdx[t * NSEL + tid];
    if (tid < NHEAD) { mS[tid] = -1e30f; lS[tid] = 0.0f; }

    // scores-phase role: heads {2*ht, 2*ht+1}, keys {kt + 16*j}
    const int kt = tid & 15;
    const int ht = tid >> 4;        // 0..7

    // PV-phase role: split-K halves, 4 heads x 4 dims register tile
    const int ksplit = tid >> 6;    // 0 / 1
    const int tile   = tid & 63;
    const int dt     = tile & 15;   // dim tile (4 dims)
    const int htp    = tile >> 4;   // head tile (4 heads)

    float acc[4][4];
    #pragma unroll
    for (int i = 0; i < 4; ++i)
        #pragma unroll
        for (int j = 0; j < 4; ++j) acc[i][j] = 0.0f;

    __syncthreads();

    for (int s = 0; s < NSEL; ++s) {
        const int base = blkS[s] * BS;
        if (base > t) continue;            // fully-future block: uniform skip

        __syncthreads();                   // prior PV reads done before overwrite

        // ---- stage K/V block (64x64) into smem, coalesced float4 ----
        {
            const float4* Kg = reinterpret_cast<const float4*>(K + (size_t)base * DIM);
            const float4* Vg = reinterpret_cast<const float4*>(V + (size_t)base * DIM);
            int c4 = tid & 15, r0 = tid >> 4;
            #pragma unroll
            for (int rr = 0; rr < 8; ++rr) {
                int r = r0 + rr * 8;
                float4 kv = Kg[r * 16 + c4];
                float4 vv = Vg[r * 16 + c4];
                *reinterpret_cast<float4*>(&Ks[r][c4 * 4]) = kv;
                *reinterpret_cast<float4*>(&Vs[r][c4 * 4]) = vv;
            }
        }
        __syncthreads();

        // ---- scores: 2 heads x 4 keys per thread, K-dim vectorized by 4 ----
        float sum0[4] = {0.f, 0.f, 0.f, 0.f};
        float sum1[4] = {0.f, 0.f, 0.f, 0.f};
        const int h0 = 2 * ht, h1 = 2 * ht + 1;
        #pragma unroll
        for (int d4 = 0; d4 < 16; ++d4) {
            float4 q0 = *reinterpret_cast<const float4*>(&Qs[h0][d4 * 4]);
            float4 q1 = *reinterpret_cast<const float4*>(&Qs[h1][d4 * 4]);
            #pragma unroll
            for (int j = 0; j < 4; ++j) {
                float4 kk = *reinterpret_cast<const float4*>(&Ks[kt + 16 * j][d4 * 4]);
                sum0[j] += q0.x * kk.x + q0.y * kk.y + q0.z * kk.z + q0.w * kk.w;
                sum1[j] += q1.x * kk.x + q1.y * kk.y + q1.z * kk.z + q1.w * kk.w;
            }
        }
        #pragma unroll
        for (int j = 0; j < 4; ++j) {
            int key = kt + 16 * j;
            bool valid = (base + key) <= t;     // causal mask on absolute position
            Ss[h0][key] = valid ? sum0[j] * SCALE : -1e30f;
            Ss[h1][key] = valid ? sum1[j] * SCALE : -1e30f;
        }
        __syncthreads();

        // ---- online softmax update: 8 threads per head ----
        {
            int h = tid >> 3, sub = tid & 7;
            float vals[8], mx = -1e30f;
            #pragma unroll
            for (int j = 0; j < 8; ++j) {
                vals[j] = Ss[h][sub * 8 + j];
                mx = fmaxf(mx, vals[j]);
            }
            #pragma unroll
            for (int off = 1; off < 8; off <<= 1)
                mx = fmaxf(mx, __shfl_xor_sync(0xffffffffu, mx, off));
            float m_old = mS[h];
            float m_new = fmaxf(m_old, mx);
            float part = 0.0f;
            #pragma unroll
            for (int j = 0; j < 8; ++j) {
                float p = __expf(vals[j] - m_new);
                Ss[h][sub * 8 + j] = p;
                part += p;
            }
            #pragma unroll
            for (int off = 1; off < 8; off <<= 1)
                part += __shfl_xor_sync(0xffffffffu, part, off);
            if (sub == 0) {
                float alpha = __expf(m_old - m_new);   // 0 when m_old = -1e30
                aS[h] = alpha;
                mS[h] = m_new;
                lS[h] = lS[h] * alpha + part;
            }
        }
        __syncthreads();

        // ---- PV accumulate: acc = acc*alpha + P.V  (split-K over 32 keys) ----
        {
            float al[4];
            #pragma unroll
            for (int i = 0; i < 4; ++i) al[i] = aS[4 * htp + i];
            #pragma unroll
            for (int i = 0; i < 4; ++i)
                #pragma unroll
                for (int j = 0; j < 4; ++j) acc[i][j] *= al[i];
            const int k0 = ksplit * 32;
            #pragma unroll 8
            for (int k = 0; k < 32; ++k) {
                int key = k0 + k;
                float4 vv = *reinterpret_cast<const float4*>(&Vs[key][dt * 4]);
                #pragma unroll
                for (int i = 0; i < 4; ++i) {
                    float p = Ss[4 * htp + i][key];
                    acc[i][0] += p * vv.x;
                    acc[i][1] += p * vv.y;
                    acc[i][2] += p * vv.z;
                    acc[i][3] += p * vv.w;
                }
            }
        }
    }

    // ---- combine the two K-splits through smem, divide by l, write out ----
    __syncthreads();
    if (ksplit == 0) {
        #pragma unroll
        for (int i = 0; i < 4; ++i)
            *reinterpret_cast<float4*>(&Ss[4 * htp + i][dt * 4]) =
                make_float4(acc[i][0], acc[i][1], acc[i][2], acc[i][3]);
    }
    __syncthreads();
    if (ksplit == 1) {
        #pragma unroll
        for (int i = 0; i < 4; ++i) {
            int h = 4 * htp + i;
            float4 o = *reinterpret_cast<const float4*>(&Ss[h][dt * 4]);
            float inv = 1.0f / lS[h];
            o.x = (o.x + acc[i][0]) * inv;
            o.y = (o.y + acc[i][1]) * inv;
            o.z = (o.z + acc[i][2]) * inv;
            o.w = (o.w + acc[i][3]) * inv;
            *reinterpret_cast<float4*>(&Out[((size_t)t * NHEAD + h) * DIM + dt * 4]) = o;
        }
    }
}

extern "C" void kernel_launch(void* const* d_in, const int* in_sizes, int n_in,
                              void* d_out, int out_size)
{
    const float* Q    = (const float*)d_in[0];
    const float* K    = (const float*)d_in[1];
    const float* V    = (const float*)d_in[2];
    const int*   BIdx = (const int*)d_in[3];
    float*       Out  = (float*)d_out;

    const int T = in_sizes[0] / (NHEAD * DIM);   // 2048
    nsa_kernel<<<T, 128>>>(Q, K, V, BIdx, Out);
}

// round 5
// speedup vs baseline: 2.2542x; 2.2542x over previous
#include <cuda_runtime.h>
#include <cuda_bf16.h>
#include <cstdint>

#define NHEAD 16
#define DIM   64
#define BS    64
#define NSEL  16
#define SCALE 0.125f
#define STRIDE 68            // floats per smem row; 68%32==4 -> (4r+c) bank pattern
#define FULL 0xffffffffu

__device__ __forceinline__ unsigned f2tf(float f) {
    unsigned r; asm("cvt.rna.tf32.f32 %0, %1;" : "=r"(r) : "f"(f)); return r;
}

__device__ __forceinline__ void mma_tf32(float c[4], const unsigned a[4],
                                         unsigned b0, unsigned b1) {
    asm volatile(
        "mma.sync.aligned.m16n8k8.row.col.f32.tf32.tf32.f32 "
        "{%0,%1,%2,%3}, {%4,%5,%6,%7}, {%8,%9}, {%0,%1,%2,%3};\n"
        : "+f"(c[0]), "+f"(c[1]), "+f"(c[2]), "+f"(c[3])
        : "r"(a[0]), "r"(a[1]), "r"(a[2]), "r"(a[3]), "r"(b0), "r"(b1));
}

__device__ __forceinline__ void cpa16(uint32_t saddr, const void* gaddr) {
    asm volatile("cp.async.cg.shared.global [%0], [%1], 16;\n"
                 :: "r"(saddr), "l"(gaddr));
}
__device__ __forceinline__ void cpa_commit() {
    asm volatile("cp.async.commit_group;\n");
}
template <int N>
__device__ __forceinline__ void cpa_wait() {
    asm volatile("cp.async.wait_group %0;\n" :: "n"(N));
}

__global__ __launch_bounds__(32, 12)
void nsa_tc_kernel(const float* __restrict__ Q, const float* __restrict__ K,
                   const float* __restrict__ V, const int* __restrict__ BIdx,
                   float* __restrict__ Out)
{
    const int t  = blockIdx.x;
    const int ln = threadIdx.x;
    const int r4 = ln >> 2;          // 0..7  (fragment "group")
    const int c4 = ln & 3;           // 0..3  (thread in group)

    __shared__ __align__(16) float Ks[32][STRIDE];
    __shared__ __align__(16) float Vs[32][STRIDE];

    // ---- stage Q (16x64) through Ks, build resident tf32 A-fragments ----
    {
        const float4* Qg = reinterpret_cast<const float4*>(Q + (size_t)t * NHEAD * DIM);
        #pragma unroll
        for (int i = 0; i < 8; ++i) {
            int e = ln + 32 * i;
            *reinterpret_cast<float4*>(&Ks[e >> 4][(e & 15) * 4]) = Qg[e];
        }
    }
    __syncwarp();
    unsigned qa[8][4];
    #pragma unroll
    for (int kc = 0; kc < 8; ++kc) {
        qa[kc][0] = f2tf(Ks[r4    ][kc * 8 + c4    ] * SCALE);
        qa[kc][1] = f2tf(Ks[r4 + 8][kc * 8 + c4    ] * SCALE);
        qa[kc][2] = f2tf(Ks[r4    ][kc * 8 + c4 + 4] * SCALE);
        qa[kc][3] = f2tf(Ks[r4 + 8][kc * 8 + c4 + 4] * SCALE);
    }
    __syncwarp();

    int myblk = (ln < NSEL) ? BIdx[t * NSEL + ln] : 0;

    float oc[8][4];
    #pragma unroll
    for (int i = 0; i < 8; ++i) { oc[i][0] = oc[i][1] = oc[i][2] = oc[i][3] = 0.f; }
    float m0 = -1e30f, m1 = -1e30f, l0 = 0.f, l1 = 0.f;

    const uint32_t ks_base = (uint32_t)__cvta_generic_to_shared(&Ks[0][0]);
    const uint32_t vs_base = (uint32_t)__cvta_generic_to_shared(&Vs[0][0]);

    for (int s = 0; s < NSEL; ++s) {
        const int base = __shfl_sync(FULL, myblk, s) * BS;
        if (base > t) continue;                    // fully-future block

        #pragma unroll
        for (int h = 0; h < 2; ++h) {
            const int kbase = base + 32 * h;
            if (kbase > t) break;                  // fully-future half

            // ---- stage K half (group depth 1), then V half (depth 0) ----
            {
                const char* Kg = reinterpret_cast<const char*>(K + (size_t)kbase * DIM);
                const char* Vg = reinterpret_cast<const char*>(V + (size_t)kbase * DIM);
                #pragma unroll
                for (int i = 0; i < 16; ++i) {
                    int e = ln + 32 * i;
                    uint32_t off = (uint32_t)((e >> 4) * STRIDE + (e & 15) * 4) * 4u;
                    cpa16(ks_base + off, Kg + e * 16);
                }
                cpa_commit();
                #pragma unroll
                for (int i = 0; i < 16; ++i) {
                    int e = ln + 32 * i;
                    uint32_t off = (uint32_t)((e >> 4) * STRIDE + (e & 15) * 4) * 4u;
                    cpa16(vs_base + off, Vg + e * 16);
                }
                cpa_commit();
            }
            cpa_wait<1>();                          // K ready (V in flight)
            __syncwarp();

            // ---- QK: 4 key-tiles x 8 k-chunks of tf32 mma ----
            float sc[4][4];
            #pragma unroll
            for (int nt = 0; nt < 4; ++nt) { sc[nt][0] = sc[nt][1] = sc[nt][2] = sc[nt][3] = 0.f; }
            #pragma unroll
            for (int nt = 0; nt < 4; ++nt) {
                #pragma unroll
                for (int kc = 0; kc < 8; ++kc) {
                    unsigned b0 = f2tf(Ks[nt * 8 + r4][kc * 8 + c4    ]);
                    unsigned b1 = f2tf(Ks[nt * 8 + r4][kc * 8 + c4 + 4]);
                    mma_tf32(sc[nt], qa[kc], b0, b1);
                }
            }

            // ---- causal mask + online softmax (registers + quad shuffles) ----
            float mx0 = -1e30f, mx1 = -1e30f;
            #pragma unroll
            for (int nt = 0; nt < 4; ++nt) {
                int p0 = kbase + nt * 8 + 2 * c4;
                if (p0     > t) { sc[nt][0] = -1e30f; sc[nt][2] = -1e30f; }
                if (p0 + 1 > t) { sc[nt][1] = -1e30f; sc[nt][3] = -1e30f; }
                mx0 = fmaxf(mx0, fmaxf(sc[nt][0], sc[nt][1]));
                mx1 = fmaxf(mx1, fmaxf(sc[nt][2], sc[nt][3]));
            }
            #pragma unroll
            for (int o = 1; o < 4; o <<= 1) {
                mx0 = fmaxf(mx0, __shfl_xor_sync(FULL, mx0, o));
                mx1 = fmaxf(mx1, __shfl_xor_sync(FULL, mx1, o));
            }
            float mn0 = fmaxf(m0, mx0), mn1 = fmaxf(m1, mx1);
            float al0 = __expf(m0 - mn0), al1 = __expf(m1 - mn1);
            m0 = mn0; m1 = mn1;
            float sum0 = 0.f, sum1 = 0.f;
            #pragma unroll
            for (int nt = 0; nt < 4; ++nt) {
                sc[nt][0] = __expf(sc[nt][0] - mn0);
                sc[nt][1] = __expf(sc[nt][1] - mn0);
                sc[nt][2] = __expf(sc[nt][2] - mn1);
                sc[nt][3] = __expf(sc[nt][3] - mn1);
                sum0 += sc[nt][0] + sc[nt][1];
                sum1 += sc[nt][2] + sc[nt][3];
            }
            #pragma unroll
            for (int o = 1; o < 4; o <<= 1) {
                sum0 += __shfl_xor_sync(FULL, sum0, o);
                sum1 += __shfl_xor_sync(FULL, sum1, o);
            }
            l0 = l0 * al0 + sum0;
            l1 = l1 * al1 + sum1;
            #pragma unroll
            for (int nt = 0; nt < 8; ++nt) {
                oc[nt][0] *= al0; oc[nt][1] *= al0;
                oc[nt][2] *= al1; oc[nt][3] *= al1;
            }

            // ---- P: C-fragment -> A-fragment via quad shuffles ----
            unsigned pa[4][4];
            {
                int srcA = (ln & ~3) | (c4 >> 1);
                int srcB = srcA + 2;
                bool par = (c4 & 1);
                #pragma unroll
                for (int kk = 0; kk < 4; ++kk) {
                    float v0a = __shfl_sync(FULL, sc[kk][0], srcA);
                    float v1a = __shfl_sync(FULL, sc[kk][1], srcA);
                    float v2a = __shfl_sync(FULL, sc[kk][2], srcA);
                    float v3a = __shfl_sync(FULL, sc[kk][3], srcA);
                    float v0b = __shfl_sync(FULL, sc[kk][0], srcB);
                    float v1b = __shfl_sync(FULL, sc[kk][1], srcB);
                    float v2b = __shfl_sync(FULL, sc[kk][2], srcB);
                    float v3b = __shfl_sync(FULL, sc[kk][3], srcB);
                    pa[kk][0] = f2tf(par ? v1a : v0a);
                    pa[kk][1] = f2tf(par ? v3a : v2a);
                    pa[kk][2] = f2tf(par ? v1b : v0b);
                    pa[kk][3] = f2tf(par ? v3b : v2b);
                }
            }

            // ---- PV: wait V, 8 dim-tiles x 4 key-chunks ----
            cpa_wait<0>();
            __syncwarp();
            #pragma unroll
            for (int nt = 0; nt < 8; ++nt) {
                #pragma unroll
                for (int kk = 0; kk < 4; ++kk) {
                    unsigned b0 = f2tf(Vs[kk * 8 + c4    ][nt * 8 + r4]);
                    unsigned b1 = f2tf(Vs[kk * 8 + c4 + 4][nt * 8 + r4]);
                    mma_tf32(oc[nt], pa[kk], b0, b1);
                }
            }
            __syncwarp();   // smem reads done before next half overwrites buffers
        }
    }

    // ---- normalize + write: rows r4 / r4+8, float2 per tile ----
    float inv0 = 1.0f / l0, inv1 = 1.0f / l1;
    float* Og = Out + (size_t)t * NHEAD * DIM;
    #pragma unroll
    for (int nt = 0; nt < 8; ++nt) {
        int col = nt * 8 + 2 * c4;
        *reinterpret_cast<float2*>(&Og[r4 * DIM + col]) =
            make_float2(oc[nt][0] * inv0, oc[nt][1] * inv0);
        *reinterpret_cast<float2*>(&Og[(r4 + 8) * DIM + col]) =
            make_float2(oc[nt][2] * inv1, oc[nt][3] * inv1);
    }
}

extern "C" void kernel_launch(void* const* d_in, const int* in_sizes, int n_in,
                              void* d_out, int out_size)
{
    const float* Q    = (const float*)d_in[0];
    const float* K    = (const float*)d_in[1];
    const float* V    = (const float*)d_in[2];
    const int*   BIdx = (const int*)d_in[3];
    float*       Out  = (float*)d_out;

    const int T = in_sizes[0] / (NHEAD * DIM);   // 2048
    nsa_tc_kernel<<<T, 32>>>(Q, K, V, BIdx, Out);
}

// round 6
// speedup vs baseline: 2.3042x; 1.0222x over previous
#include <cuda_runtime.h>
#include <cuda_bf16.h>
#include <cstdint>

#define NHEAD 16
#define DIM   64
#define BS    64
#define NSEL  16
// SCALE * log2(e): softmax runs in base-2 domain
#define SCALE2 0.18033688011112042f
#define STRIDE 68            // floats per smem row; 68%32==4 -> (4r+c) bank pattern
#define FULL 0xffffffffu

__device__ __forceinline__ unsigned f2tf(float f) {
    unsigned r; asm("cvt.rna.tf32.f32 %0, %1;" : "=r"(r) : "f"(f)); return r;
}

__device__ __forceinline__ void mma_tf32(float c[4], const unsigned a[4],
                                         unsigned b0, unsigned b1) {
    asm volatile(
        "mma.sync.aligned.m16n8k8.row.col.f32.tf32.tf32.f32 "
        "{%0,%1,%2,%3}, {%4,%5,%6,%7}, {%8,%9}, {%0,%1,%2,%3};\n"
        : "+f"(c[0]), "+f"(c[1]), "+f"(c[2]), "+f"(c[3])
        : "r"(a[0]), "r"(a[1]), "r"(a[2]), "r"(a[3]), "r"(b0), "r"(b1));
}

__device__ __forceinline__ void cpa16(uint32_t saddr, const void* gaddr) {
    asm volatile("cp.async.cg.shared.global [%0], [%1], 16;\n"
                 :: "r"(saddr), "l"(gaddr));
}
__device__ __forceinline__ void cpa_commit() {
    asm volatile("cp.async.commit_group;\n");
}
template <int N>
__device__ __forceinline__ void cpa_wait() {
    asm volatile("cp.async.wait_group %0;\n" :: "n"(N));
}

__global__ __launch_bounds__(32, 13)
void nsa_tc_kernel(const float* __restrict__ Q, const float* __restrict__ K,
                   const float* __restrict__ V, const int* __restrict__ BIdx,
                   float* __restrict__ Out)
{
    // Reverse mapping: expensive tokens (large t = most valid blocks) start
    // first; the partial last wave gets the cheapest tokens.
    const int t  = (int)gridDim.x - 1 - (int)blockIdx.x;
    const int ln = threadIdx.x;
    const int r4 = ln >> 2;          // 0..7  (fragment "group")
    const int c4 = ln & 3;           // 0..3  (thread in group)

    __shared__ __align__(16) float Ks[32][STRIDE];
    __shared__ __align__(16) float Vs[32][STRIDE];

    // ---- stage Q (16x64) through Ks, build resident tf32 A-fragments ----
    {
        const float4* Qg = reinterpret_cast<const float4*>(Q + (size_t)t * NHEAD * DIM);
        #pragma unroll
        for (int i = 0; i < 8; ++i) {
            int e = ln + 32 * i;
            *reinterpret_cast<float4*>(&Ks[e >> 4][(e & 15) * 4]) = Qg[e];
        }
    }
    __syncwarp();
    unsigned qa[8][4];
    #pragma unroll
    for (int kc = 0; kc < 8; ++kc) {
        qa[kc][0] = f2tf(Ks[r4    ][kc * 8 + c4    ] * SCALE2);
        qa[kc][1] = f2tf(Ks[r4 + 8][kc * 8 + c4    ] * SCALE2);
        qa[kc][2] = f2tf(Ks[r4    ][kc * 8 + c4 + 4] * SCALE2);
        qa[kc][3] = f2tf(Ks[r4 + 8][kc * 8 + c4 + 4] * SCALE2);
    }
    __syncwarp();

    int myblk = (ln < NSEL) ? BIdx[t * NSEL + ln] : 0;

    float oc[8][4];
    #pragma unroll
    for (int i = 0; i < 8; ++i) { oc[i][0] = oc[i][1] = oc[i][2] = oc[i][3] = 0.f; }
    float m0 = -1e30f, m1 = -1e30f, l0 = 0.f, l1 = 0.f;

    const uint32_t ks_base = (uint32_t)__cvta_generic_to_shared(&Ks[0][0]);
    const uint32_t vs_base = (uint32_t)__cvta_generic_to_shared(&Vs[0][0]);

    for (int s = 0; s < NSEL; ++s) {
        const int base = __shfl_sync(FULL, myblk, s) * BS;
        if (base > t) continue;                    // fully-future block

        #pragma unroll
        for (int h = 0; h < 2; ++h) {
            const int kbase = base + 32 * h;
            if (kbase > t) break;                  // fully-future half

            // ---- stage K half (group depth 1), then V half (depth 0) ----
            {
                const char* Kg = reinterpret_cast<const char*>(K + (size_t)kbase * DIM);
                const char* Vg = reinterpret_cast<const char*>(V + (size_t)kbase * DIM);
                #pragma unroll
                for (int i = 0; i < 16; ++i) {
                    int e = ln + 32 * i;
                    uint32_t off = (uint32_t)((e >> 4) * STRIDE + (e & 15) * 4) * 4u;
                    cpa16(ks_base + off, Kg + e * 16);
                }
                cpa_commit();
                #pragma unroll
                for (int i = 0; i < 16; ++i) {
                    int e = ln + 32 * i;
                    uint32_t off = (uint32_t)((e >> 4) * STRIDE + (e & 15) * 4) * 4u;
                    cpa16(vs_base + off, Vg + e * 16);
                }
                cpa_commit();
            }
            cpa_wait<1>();                          // K ready (V in flight)
            __syncwarp();

            // ---- QK: 4 key-tiles x 8 k-chunks of tf32 mma ----
            // B operands: raw fp32 bits (HW truncates to tf32; rna kept on A side)
            float sc[4][4];
            #pragma unroll
            for (int nt = 0; nt < 4; ++nt) { sc[nt][0] = sc[nt][1] = sc[nt][2] = sc[nt][3] = 0.f; }
            #pragma unroll
            for (int nt = 0; nt < 4; ++nt) {
                #pragma unroll
                for (int kc = 0; kc < 8; ++kc) {
                    unsigned b0 = __float_as_uint(Ks[nt * 8 + r4][kc * 8 + c4    ]);
                    unsigned b1 = __float_as_uint(Ks[nt * 8 + r4][kc * 8 + c4 + 4]);
                    mma_tf32(sc[nt], qa[kc], b0, b1);
                }
            }

            // ---- causal mask + online softmax (base-2 domain, quad shuffles) ----
            float mx0 = -1e30f, mx1 = -1e30f;
            #pragma unroll
            for (int nt = 0; nt < 4; ++nt) {
                int p0 = kbase + nt * 8 + 2 * c4;
                if (p0     > t) { sc[nt][0] = -1e30f; sc[nt][2] = -1e30f; }
                if (p0 + 1 > t) { sc[nt][1] = -1e30f; sc[nt][3] = -1e30f; }
                mx0 = fmaxf(mx0, fmaxf(sc[nt][0], sc[nt][1]));
                mx1 = fmaxf(mx1, fmaxf(sc[nt][2], sc[nt][3]));
            }
            #pragma unroll
            for (int o = 1; o < 4; o <<= 1) {
                mx0 = fmaxf(mx0, __shfl_xor_sync(FULL, mx0, o));
                mx1 = fmaxf(mx1, __shfl_xor_sync(FULL, mx1, o));
            }
            float mn0 = fmaxf(m0, mx0), mn1 = fmaxf(m1, mx1);
            float al0 = exp2f(m0 - mn0), al1 = exp2f(m1 - mn1);
            m0 = mn0; m1 = mn1;
            float sum0 = 0.f, sum1 = 0.f;
            #pragma unroll
            for (int nt = 0; nt < 4; ++nt) {
                sc[nt][0] = exp2f(sc[nt][0] - mn0);
                sc[nt][1] = exp2f(sc[nt][1] - mn0);
                sc[nt][2] = exp2f(sc[nt][2] - mn1);
                sc[nt][3] = exp2f(sc[nt][3] - mn1);
                sum0 += sc[nt][0] + sc[nt][1];
                sum1 += sc[nt][2] + sc[nt][3];
            }
            #pragma unroll
            for (int o = 1; o < 4; o <<= 1) {
                sum0 += __shfl_xor_sync(FULL, sum0, o);
                sum1 += __shfl_xor_sync(FULL, sum1, o);
            }
            l0 = l0 * al0 + sum0;
            l1 = l1 * al1 + sum1;
            #pragma unroll
            for (int nt = 0; nt < 8; ++nt) {
                oc[nt][0] *= al0; oc[nt][1] *= al0;
                oc[nt][2] *= al1; oc[nt][3] *= al1;
            }

            // ---- P: C-fragment -> A-fragment via quad shuffles ----
            unsigned pa[4][4];
            {
                int srcA = (ln & ~3) | (c4 >> 1);
                int srcB = srcA + 2;
                bool par = (c4 & 1);
                #pragma unroll
                for (int kk = 0; kk < 4; ++kk) {
                    float v0a = __shfl_sync(FULL, sc[kk][0], srcA);
                    float v1a = __shfl_sync(FULL, sc[kk][1], srcA);
                    float v2a = __shfl_sync(FULL, sc[kk][2], srcA);
                    float v3a = __shfl_sync(FULL, sc[kk][3], srcA);
                    float v0b = __shfl_sync(FULL, sc[kk][0], srcB);
                    float v1b = __shfl_sync(FULL, sc[kk][1], srcB);
                    float v2b = __shfl_sync(FULL, sc[kk][2], srcB);
                    float v3b = __shfl_sync(FULL, sc[kk][3], srcB);
                    pa[kk][0] = f2tf(par ? v1a : v0a);
                    pa[kk][1] = f2tf(par ? v3a : v2a);
                    pa[kk][2] = f2tf(par ? v1b : v0b);
                    pa[kk][3] = f2tf(par ? v3b : v2b);
                }
            }

            // ---- PV: wait V, 8 dim-tiles x 4 key-chunks ----
            cpa_wait<0>();
            __syncwarp();
            #pragma unroll
            for (int nt = 0; nt < 8; ++nt) {
                #pragma unroll
                for (int kk = 0; kk < 4; ++kk) {
                    unsigned b0 = __float_as_uint(Vs[kk * 8 + c4    ][nt * 8 + r4]);
                    unsigned b1 = __float_as_uint(Vs[kk * 8 + c4 + 4][nt * 8 + r4]);
                    mma_tf32(oc[nt], pa[kk], b0, b1);
                }
            }
            __syncwarp();   // smem reads done before next half overwrites buffers
        }
    }

    // ---- normalize + write: rows r4 / r4+8, float2 per tile ----
    float inv0 = 1.0f / l0, inv1 = 1.0f / l1;
    float* Og = Out + (size_t)t * NHEAD * DIM;
    #pragma unroll
    for (int nt = 0; nt < 8; ++nt) {
        int col = nt * 8 + 2 * c4;
        *reinterpret_cast<float2*>(&Og[r4 * DIM + col]) =
            make_float2(oc[nt][0] * inv0, oc[nt][1] * inv0);
        *reinterpret_cast<float2*>(&Og[(r4 + 8) * DIM + col]) =
            make_float2(oc[nt][2] * inv1, oc[nt][3] * inv1);
    }
}

extern "C" void kernel_launch(void* const* d_in, const int* in_sizes, int n_in,
                              void* d_out, int out_size)
{
    const float* Q    = (const float*)d_in[0];
    const float* K    = (const float*)d_in[1];
    const float* V    = (const float*)d_in[2];
    const int*   BIdx = (const int*)d_in[3];
    float*       Out  = (float*)d_out;

    const int T = in_sizes[0] / (NHEAD * DIM);   // 2048
    nsa_tc_kernel<<<T, 32>>>(Q, K, V, BIdx, Out);
}